// round 15
// baseline (speedup 1.0000x reference)
#include <cuda_runtime.h>

#define NB 4096
#define L 64
#define D 128
#define TMAX 65            // counts are in [0, 64]
#define NUM_IDS 1000
#define NWORDS 250         // 1000 ids, 4 byte-counters per word
#define GRID NB            // one batch per block
#define THREADS 128

// Lookup table: T[a][e] = sum_d relu(a*W1[d]+b1[d]) * W2[d][e] + b2[e]
__device__ float g_T[TMAX * D];
__device__ unsigned int g_done = 0;   // monotonic; >=65 once table built (replays: builders rewrite identical values)

// Champion form (R11/R14, 43.4-43.5us total). Sole change this round: __stwt
// (write-through) instead of __stcs — completes the store cache-op sweep
// (.cs champion / .wb regressed / .wt untested). Full-512B-per-warp contiguous
// segments make write-through granularity-safe.
__global__ __launch_bounds__(THREADS) void nif_fused_kernel(
    const int* __restrict__ src_ids, const int* __restrict__ dst_ids,
    const int* __restrict__ src_nb,  const int* __restrict__ dst_nb,
    const float* __restrict__ W1, const float* __restrict__ b1,
    const float* __restrict__ W2, const float* __restrict__ b2,
    float* __restrict__ out)
{
    __shared__ unsigned int s_cnt[2][NWORDS];   // byte-packed counts, 2 KB
    __shared__ int   s_a[2 * L];                // packed a0 | (a1<<8)
    __shared__ float s_h[D];                    // builder scratch

    const int tid  = threadIdx.x;               // 0..127
    const int lane = tid & 31;
    const int wrp  = tid >> 5;                  // 0..3
    const int b    = blockIdx.x;
    const size_t half = (size_t)NB * L * D;
    const float4* gT4 = (const float4*)g_T;     // [TMAX][32] float4

    // ================= table-builder role: blocks 0..64 =================
    if (b < TMAX) {
        s_h[tid] = fmaxf((float)b * W1[tid] + b1[tid], 0.0f);
        __syncthreads();
        float acc = b2[tid];
        #pragma unroll 8
        for (int d = 0; d < D; ++d)
            acc = fmaf(s_h[d], W2[d * D + tid], acc);
        g_T[b * D + tid] = acc;
        __syncthreads();
        if (tid == 0) {
            __threadfence();                    // release table writes
            atomicAdd(&g_done, 1u);
        }
    }

    // ================= histogram phase (table-independent) ===============
    {
        unsigned int* z = &s_cnt[0][0];
        #pragma unroll
        for (int i = tid; i < 2 * NWORDS; i += THREADS) z[i] = 0u;
    }
    __syncthreads();

    const int lst  = (tid < L) ? 0 : 1;                     // 0 = src list, 1 = dst list
    const int my_x = (tid < L) ? __ldg(&src_nb[b * L + tid])
                               : __ldg(&dst_nb[b * L + (tid - L)]);
    atomicAdd(&s_cnt[lst][my_x >> 2], 1u << ((my_x & 3) * 8));
    __syncthreads();

    // ---- counts + dict-mutation overrides (exact reference semantics) ----
    {
        const int sid = __ldg(&src_ids[b]);
        const int did = __ldg(&dst_ids[b]);
        const int cd  = (s_cnt[1][sid >> 2] >> ((sid & 3) * 8)) & 0xFF;  // src_id in dst list
        const int cs  = (s_cnt[0][did >> 2] >> ((did & 3) * 8)) & 0xFF;  // dst_id in src list
        const bool same   = (sid == did);
        const bool in_dst = (cd > 0);                       // srcid_in_dst
        const bool cond2  = (cs > 0) || (same && in_dst);
        const int  v2     = (same && in_dst) ? cd : cs;

        const int c_self  = (s_cnt[lst][my_x >> 2]     >> ((my_x & 3) * 8)) & 0xFF;
        const int c_other = (s_cnt[lst ^ 1][my_x >> 2] >> ((my_x & 3) * 8)) & 0xFF;
        int a0, a1;
        if (tid < L) {
            a0 = c_self;                                    // c_src
            a1 = (my_x == did && cond2)  ? v2 : c_other;    // src_col1
        } else {
            a0 = (my_x == sid && in_dst) ? cd : c_other;    // dst_col0
            a1 = c_self;                                    // c_dst
        }
        s_a[tid] = a0 | (a1 << 8);
    }

    // ================= wait for the table (usually already done) =========
    if (tid == 0) {
        unsigned int v;
        do {
            asm volatile("ld.acquire.gpu.u32 %0, [%1];" : "=r"(v) : "l"(&g_done) : "memory");
        } while (v < TMAX);
    }
    __syncthreads();

    // hot table rows (a=0,1 cover ~97%); S = T0+T1 is the common row sum
    const float4 t0r = __ldg(&gT4[0 * 32 + lane]);
    const float4 t1r = __ldg(&gT4[1 * 32 + lane]);
    float4 S;
    S.x = t0r.x + t1r.x; S.y = t0r.y + t1r.y;
    S.z = t0r.z + t1r.z; S.w = t0r.w + t1r.w;

    // ================= barrier-free streaming store ======================
    // warp w: isdst = w>>1, r0 = (w&1)*32 -> 32 contiguous rows per warp
    {
        const int isdst = wrp >> 1;
        const int r0    = (wrp & 1) * 32;
        float4* ptr = (float4*)(out + (isdst ? half : 0)
                                + (size_t)b * L * D + r0 * D) + lane;
        const int* sa = &s_a[isdst * L + r0];

        #pragma unroll
        for (int i = 0; i < 32; ++i) {
            const int packed = sa[i];                        // warp-uniform broadcast
            float4 o;
            if (packed == 1 || packed == 256) {              // (1,0) or (0,1): ~88%
                o = S;
            } else {                                         // warp-uniform rare path
                const int a0 = packed & 0xFF;
                const int a1 = packed >> 8;
                const float4 ta = __ldg(&gT4[a0 * 32 + lane]);
                const float4 tb = __ldg(&gT4[a1 * 32 + lane]);
                o.x = ta.x + tb.x; o.y = ta.y + tb.y;
                o.z = ta.z + tb.z; o.w = ta.w + tb.w;
            }
            __stwt(ptr + i * (D / 4), o);                    // write-through store
        }
    }
}

extern "C" void kernel_launch(void* const* d_in, const int* in_sizes, int n_in,
                              void* d_out, int out_size)
{
    const int*   src_ids = (const int*)  d_in[0];
    const int*   dst_ids = (const int*)  d_in[1];
    const int*   src_nb  = (const int*)  d_in[2];
    const int*   dst_nb  = (const int*)  d_in[3];
    const float* W1      = (const float*)d_in[4];
    const float* b1      = (const float*)d_in[5];
    const float* W2      = (const float*)d_in[6];
    const float* b2      = (const float*)d_in[7];
    float*       out     = (float*)d_out;

    nif_fused_kernel<<<GRID, THREADS>>>(src_ids, dst_ids, src_nb, dst_nb,
                                        W1, b1, W2, b2, out);
}

// round 16
// speedup vs baseline: 1.0647x; 1.0647x over previous
#include <cuda_runtime.h>

#define NB 4096
#define L 64
#define D 128
#define TMAX 65            // counts are in [0, 64]
#define NUM_IDS 1000
#define NWORDS 250         // 1000 ids, 4 byte-counters per word
#define GRID NB            // one batch per block
#define THREADS 128

// Lookup table: T[a][e] = sum_d relu(a*W1[d]+b1[d]) * W2[d][e] + b2[e]
__device__ float g_T[TMAX * D];
__device__ unsigned int g_done = 0;   // monotonic; >=65 once table built (replays: builders rewrite identical values)

// FINAL FORM (R11/R14 champion, 43.39/43.49us total, twice reproduced).
// Converged at the HBM pure-write ceiling (~5.0 TB/s, DRAM ~62%, no pipe
// saturated). Measured regressions close every remaining axis:
//   - launch_bounds minblocks 8/6 (R8 spills +50% DRAM bytes; R9 codegen perturbation)
//   - BPB=4 / grid=1024 (R12: occupancy collapse to 38%)
//   - store .wb (R13: +1.5us, L2 thrash) and .wt (R15: +1.2us) vs .cs champion
// Structure: fused table-builder (blocks 0..64) + spin-gate, byte-packed smem
// histogram counting (O(L) per thread), hot-row register cache (a<=1 covers
// ~97% of lookups), barrier-free __stcs float4 store stream.
__global__ __launch_bounds__(THREADS) void nif_fused_kernel(
    const int* __restrict__ src_ids, const int* __restrict__ dst_ids,
    const int* __restrict__ src_nb,  const int* __restrict__ dst_nb,
    const float* __restrict__ W1, const float* __restrict__ b1,
    const float* __restrict__ W2, const float* __restrict__ b2,
    float* __restrict__ out)
{
    __shared__ unsigned int s_cnt[2][NWORDS];   // byte-packed counts, 2 KB
    __shared__ int   s_a[2 * L];                // packed a0 | (a1<<8)
    __shared__ float s_h[D];                    // builder scratch

    const int tid  = threadIdx.x;               // 0..127
    const int lane = tid & 31;
    const int wrp  = tid >> 5;                  // 0..3
    const int b    = blockIdx.x;
    const size_t half = (size_t)NB * L * D;
    const float4* gT4 = (const float4*)g_T;     // [TMAX][32] float4

    // ================= table-builder role: blocks 0..64 =================
    if (b < TMAX) {
        s_h[tid] = fmaxf((float)b * W1[tid] + b1[tid], 0.0f);
        __syncthreads();
        float acc = b2[tid];
        #pragma unroll 8
        for (int d = 0; d < D; ++d)
            acc = fmaf(s_h[d], W2[d * D + tid], acc);
        g_T[b * D + tid] = acc;
        __syncthreads();
        if (tid == 0) {
            __threadfence();                    // release table writes
            atomicAdd(&g_done, 1u);
        }
    }

    // ================= histogram phase (table-independent) ===============
    {
        unsigned int* z = &s_cnt[0][0];
        #pragma unroll
        for (int i = tid; i < 2 * NWORDS; i += THREADS) z[i] = 0u;
    }
    __syncthreads();

    const int lst  = (tid < L) ? 0 : 1;                     // 0 = src list, 1 = dst list
    const int my_x = (tid < L) ? __ldg(&src_nb[b * L + tid])
                               : __ldg(&dst_nb[b * L + (tid - L)]);
    atomicAdd(&s_cnt[lst][my_x >> 2], 1u << ((my_x & 3) * 8));
    __syncthreads();

    // ---- counts + dict-mutation overrides (exact reference semantics) ----
    {
        const int sid = __ldg(&src_ids[b]);
        const int did = __ldg(&dst_ids[b]);
        const int cd  = (s_cnt[1][sid >> 2] >> ((sid & 3) * 8)) & 0xFF;  // src_id in dst list
        const int cs  = (s_cnt[0][did >> 2] >> ((did & 3) * 8)) & 0xFF;  // dst_id in src list
        const bool same   = (sid == did);
        const bool in_dst = (cd > 0);                       // srcid_in_dst
        const bool cond2  = (cs > 0) || (same && in_dst);
        const int  v2     = (same && in_dst) ? cd : cs;

        const int c_self  = (s_cnt[lst][my_x >> 2]     >> ((my_x & 3) * 8)) & 0xFF;
        const int c_other = (s_cnt[lst ^ 1][my_x >> 2] >> ((my_x & 3) * 8)) & 0xFF;
        int a0, a1;
        if (tid < L) {
            a0 = c_self;                                    // c_src
            a1 = (my_x == did && cond2)  ? v2 : c_other;    // src_col1
        } else {
            a0 = (my_x == sid && in_dst) ? cd : c_other;    // dst_col0
            a1 = c_self;                                    // c_dst
        }
        s_a[tid] = a0 | (a1 << 8);
    }

    // ================= wait for the table (usually already done) =========
    if (tid == 0) {
        unsigned int v;
        do {
            asm volatile("ld.acquire.gpu.u32 %0, [%1];" : "=r"(v) : "l"(&g_done) : "memory");
        } while (v < TMAX);
    }
    __syncthreads();

    // hot table rows (a=0,1 cover ~97%); S = T0+T1 is the common row sum
    const float4 t0r = __ldg(&gT4[0 * 32 + lane]);
    const float4 t1r = __ldg(&gT4[1 * 32 + lane]);
    float4 S;
    S.x = t0r.x + t1r.x; S.y = t0r.y + t1r.y;
    S.z = t0r.z + t1r.z; S.w = t0r.w + t1r.w;

    // ================= barrier-free streaming store ======================
    // warp w: isdst = w>>1, r0 = (w&1)*32 -> 32 contiguous rows per warp
    {
        const int isdst = wrp >> 1;
        const int r0    = (wrp & 1) * 32;
        float4* ptr = (float4*)(out + (isdst ? half : 0)
                                + (size_t)b * L * D + r0 * D) + lane;
        const int* sa = &s_a[isdst * L + r0];

        #pragma unroll
        for (int i = 0; i < 32; ++i) {
            const int packed = sa[i];                        // warp-uniform broadcast
            float4 o;
            if (packed == 1 || packed == 256) {              // (1,0) or (0,1): ~88%
                o = S;
            } else {                                         // warp-uniform rare path
                const int a0 = packed & 0xFF;
                const int a1 = packed >> 8;
                const float4 ta = __ldg(&gT4[a0 * 32 + lane]);
                const float4 tb = __ldg(&gT4[a1 * 32 + lane]);
                o.x = ta.x + tb.x; o.y = ta.y + tb.y;
                o.z = ta.z + tb.z; o.w = ta.w + tb.w;
            }
            __stcs(ptr + i * (D / 4), o);
        }
    }
}

extern "C" void kernel_launch(void* const* d_in, const int* in_sizes, int n_in,
                              void* d_out, int out_size)
{
    const int*   src_ids = (const int*)  d_in[0];
    const int*   dst_ids = (const int*)  d_in[1];
    const int*   src_nb  = (const int*)  d_in[2];
    const int*   dst_nb  = (const int*)  d_in[3];
    const float* W1      = (const float*)d_in[4];
    const float* b1      = (const float*)d_in[5];
    const float* W2      = (const float*)d_in[6];
    const float* b2      = (const float*)d_in[7];
    float*       out     = (float*)d_out;

    nif_fused_kernel<<<GRID, THREADS>>>(src_ids, dst_ids, src_nb, dst_nb,
                                        W1, b1, W2, b2, out);
}